// round 8
// baseline (speedup 1.0000x reference)
#include <cuda_runtime.h>
#include <math.h>

// Problem constants
#define T_LEN 512
#define B_SZ  64
#define I_SZ  512
#define H_SZ  1024
#define G3H   3072
#define M_TOT 32768          // T*B

#define NBLK  128            // persistent blocks (1 per SM)
#define JT    8              // hidden units per block
#define NROW  24             // gate rows per block (3*JT)
#define NPAIR 8              // warp pairs (k-slices)
#define KSL   128            // k-slice per pair
#define CHK   16             // k per chunk
#define HST   20             // h window stride (floats; 80B, 16B-aligned)
#define REDS  66

typedef unsigned long long ull;

__device__ __align__(16) float g_gates[(size_t)M_TOT * G3H];
__device__ __align__(16) float g_h0[B_SZ * H_SZ];  // zero-init, never written
__device__ unsigned g_sync;

// ---------------------------------------------------------------------------
// f32x2 helpers
// ---------------------------------------------------------------------------
__device__ __forceinline__ ull dup2(float w) {
    ull r; asm("mov.b64 %0, {%1, %1};" : "=l"(r) : "f"(w)); return r;
}
__device__ __forceinline__ void ffma2(ull& d, ull a, ull b) {
    asm("fma.rn.f32x2 %0, %1, %2, %0;" : "+l"(d) : "l"(a), "l"(b));
}
__device__ __forceinline__ float sum2(ull v) {
    float lo, hi;
    asm("mov.b64 {%0, %1}, %2;" : "=f"(lo), "=f"(hi) : "l"(v));
    return lo + hi;
}
__device__ __forceinline__ void unpack2(ull v, float& lo, float& hi) {
    asm("mov.b64 {%0, %1}, %2;" : "=f"(lo), "=f"(hi) : "l"(v));
}

// ---------------------------------------------------------------------------
// Kernel A: x_gates = x @ w_ih^T + b_ih.  M=32768, N=3072, K=512.
// 128x128 tile, K-tile 8, 256 threads, thread tile 8m x 8n.
// ---------------------------------------------------------------------------
__global__ __launch_bounds__(256)
void gemm_xgates(const float* __restrict__ A,
                 const float* __restrict__ W,
                 const float* __restrict__ bias)
{
    __shared__ __align__(16) float As[2][8][132];   // [kk][m]
    __shared__ __align__(16) float Bs[2][8][132];   // [kk][n]

    const int m0 = blockIdx.y * 128;
    const int n0 = blockIdx.x * 128;
    const int tid = threadIdx.x;
    const int tm = tid >> 4;
    const int tn = tid & 15;
    const int lr = tid >> 1;
    const int lk4 = (tid & 1) * 4;

    ull acc[8][4];
    #pragma unroll
    for (int i = 0; i < 8; i++)
        #pragma unroll
        for (int p = 0; p < 4; p++) acc[i][p] = 0ull;

    float4 av = *(const float4*)&A[(size_t)(m0 + lr) * I_SZ + lk4];
    float4 wv = *(const float4*)&W[(size_t)(n0 + lr) * I_SZ + lk4];
    {
        As[0][lk4 + 0][lr] = av.x; As[0][lk4 + 1][lr] = av.y;
        As[0][lk4 + 2][lr] = av.z; As[0][lk4 + 3][lr] = av.w;
        Bs[0][lk4 + 0][lr] = wv.x; Bs[0][lk4 + 1][lr] = wv.y;
        Bs[0][lk4 + 2][lr] = wv.z; Bs[0][lk4 + 3][lr] = wv.w;
    }
    __syncthreads();

    #pragma unroll 1
    for (int kt = 0; kt < 64; kt++) {
        const int buf = kt & 1;
        if (kt < 63) {
            int k0 = (kt + 1) * 8 + lk4;
            av = *(const float4*)&A[(size_t)(m0 + lr) * I_SZ + k0];
            wv = *(const float4*)&W[(size_t)(n0 + lr) * I_SZ + k0];
        }
        #pragma unroll
        for (int kk = 0; kk < 8; kk++) {
            float4 a0 = *(const float4*)&As[buf][kk][tm * 8];
            float4 a1 = *(const float4*)&As[buf][kk][tm * 8 + 4];
            ull am[8];
            am[0] = dup2(a0.x); am[1] = dup2(a0.y);
            am[2] = dup2(a0.z); am[3] = dup2(a0.w);
            am[4] = dup2(a1.x); am[5] = dup2(a1.y);
            am[6] = dup2(a1.z); am[7] = dup2(a1.w);
            ulonglong2 b0 = *(const ulonglong2*)&Bs[buf][kk][tn * 8];
            ulonglong2 b1 = *(const ulonglong2*)&Bs[buf][kk][tn * 8 + 4];
            #pragma unroll
            for (int i = 0; i < 8; i++) {
                ffma2(acc[i][0], am[i], b0.x);
                ffma2(acc[i][1], am[i], b0.y);
                ffma2(acc[i][2], am[i], b1.x);
                ffma2(acc[i][3], am[i], b1.y);
            }
        }
        if (kt < 63) {
            const int nb = buf ^ 1;
            As[nb][lk4 + 0][lr] = av.x; As[nb][lk4 + 1][lr] = av.y;
            As[nb][lk4 + 2][lr] = av.z; As[nb][lk4 + 3][lr] = av.w;
            Bs[nb][lk4 + 0][lr] = wv.x; Bs[nb][lk4 + 1][lr] = wv.y;
            Bs[nb][lk4 + 2][lr] = wv.z; Bs[nb][lk4 + 3][lr] = wv.w;
        }
        __syncthreads();
    }

    const int nn = n0 + tn * 8;
    float4 bv0 = *(const float4*)&bias[nn];
    float4 bv1 = *(const float4*)&bias[nn + 4];
    #pragma unroll
    for (int i = 0; i < 8; i++) {
        float c0, c1, c2, c3, c4, c5, c6, c7;
        unpack2(acc[i][0], c0, c1);
        unpack2(acc[i][1], c2, c3);
        unpack2(acc[i][2], c4, c5);
        unpack2(acc[i][3], c6, c7);
        float4 o0 = make_float4(c0 + bv0.x, c1 + bv0.y, c2 + bv0.z, c3 + bv0.w);
        float4 o1 = make_float4(c4 + bv1.x, c5 + bv1.y, c6 + bv1.z, c7 + bv1.w);
        int row = m0 + tm * 8 + i;
        *(float4*)&g_gates[(size_t)row * G3H + nn]     = o0;
        *(float4*)&g_gates[(size_t)row * G3H + nn + 4] = o1;
    }
}

// ---------------------------------------------------------------------------
// Persistent GRU scan kernel.
// grid = 128 blocks (1/SM), 512 threads = 16 warps = 8 pairs.
// Pair p: k-slice [p*128, p*128+128), shared h window, cooperative load.
// Warp half h of pair: gate rows [h*12, h*12+12).  12x2 = 24 f32x2 accums.
// Sync inside mainloop: bar.sync (p+1), 64  (pair-local).
// 4 warps/SMSP for latency hiding; per u: 2 h LDS + 12 W broadcast / 48 FFMA2.
// ---------------------------------------------------------------------------
__global__ void __launch_bounds__(512, 1)
gru_persistent(float* __restrict__ out,
               const float* __restrict__ w_hh,
               const float* __restrict__ b_hh)
{
    extern __shared__ __align__(16) float smem[];
    float* Ws  = smem;                          // [24][1024]
    float* Hw  = Ws + NROW * H_SZ;              // [8 p][2 buf][64][HST]
    float* Red = Hw + NPAIR * 2 * 64 * HST;     // [8 p][24][REDS]

    const int tid  = threadIdx.x;
    const int w    = tid >> 5;
    const int lane = tid & 31;
    const int p    = w >> 1;                    // pair = k-slice
    const int half = w & 1;                     // row half
    const int j0   = blockIdx.x * JT;
    const int kofs = p * KSL;
    const int rbase = half * 12;

    // ---- load W slice into smem (once); row = g*8 + jj ----
    for (int idx = tid; idx < NROW * (H_SZ / 4); idx += 512) {
        int row = idx >> 8;
        int q   = idx & 255;
        int g = row >> 3, jj = row & 7;
        *(float4*)&Ws[row * H_SZ + 4 * q] =
            *(const float4*)&w_hh[(size_t)(g * H_SZ + j0 + jj) * H_SZ + 4 * q];
    }

    // ---- epilogue mapping: one output per thread ----
    const int eb  = tid >> 3;                   // batch 0..63
    const int ejj = tid & 7;
    const int ej  = j0 + ejj;
    const float bhr = b_hh[ej];
    const float bhz = b_hh[H_SZ + ej];
    const float bhn = b_hh[2 * H_SZ + ej];

    // ---- pair loader mapping: gt in 0..63, 4 float4 each ----
    const int gt = half * 32 + lane;
    const int lb = gt >> 2;                     // 0..15 (batches lb+16i)
    const int lq = gt & 3;                      // k-quad
    float* HwP = Hw + p * (2 * 64 * HST);

    __syncthreads();

    unsigned target = NBLK;
    float* hn_out = out + (size_t)T_LEN * B_SZ * H_SZ;
    float hpv = 0.f;

    #pragma unroll 1
    for (int t = 0; t < T_LEN; t++) {
        const float* hp = (t == 0) ? g_h0
                        : out + (size_t)(t - 1) * B_SZ * H_SZ;
        float* ho = out + (size_t)t * B_SZ * H_SZ;

        // epilogue x-gate prefetch (hidden by mainloop)
        const float* xg = g_gates + (size_t)t * B_SZ * G3H
                        + (size_t)eb * G3H + ej;
        float xr = __ldcg(&xg[0]);
        float xz = __ldcg(&xg[H_SZ]);
        float xn = __ldcg(&xg[2 * H_SZ]);

        ull acc[12][2];
        #pragma unroll
        for (int i = 0; i < 12; i++) { acc[i][0] = 0ull; acc[i][1] = 0ull; }

        // chunk 0: cooperative load + stage
        float4 r4[4];
        #pragma unroll
        for (int i = 0; i < 4; i++)
            r4[i] = __ldcg((const float4*)&hp[(size_t)(lb + 16 * i) * H_SZ + kofs + lq * 4]);
        #pragma unroll
        for (int i = 0; i < 4; i++)
            *(float4*)&HwP[(lb + 16 * i) * HST + lq * 4] = r4[i];
        asm volatile("bar.sync %0, 64;" :: "r"(p + 1) : "memory");

        #pragma unroll 1
        for (int c = 0; c < 8; c++) {
            const int buf = c & 1;
            if (c < 7) {
                int kc = kofs + (c + 1) * CHK + lq * 4;
                #pragma unroll
                for (int i = 0; i < 4; i++)
                    r4[i] = __ldcg((const float4*)&hp[(size_t)(lb + 16 * i) * H_SZ + kc]);
            }
            const float* hbase = &HwP[buf * 64 * HST];
            const float* wbase = &Ws[rbase * H_SZ + kofs + c * CHK];
            #pragma unroll
            for (int u = 0; u < CHK / 4; u++) {
                ulonglong2 hA = *(const ulonglong2*)&hbase[lane * HST + u * 4];
                ulonglong2 hB = *(const ulonglong2*)&hbase[(lane + 32) * HST + u * 4];
                #pragma unroll
                for (int row = 0; row < 12; row++) {
                    ulonglong2 wv = *(const ulonglong2*)&wbase[row * H_SZ + u * 4];
                    ffma2(acc[row][0], hA.x, wv.x);
                    ffma2(acc[row][0], hA.y, wv.y);
                    ffma2(acc[row][1], hB.x, wv.x);
                    ffma2(acc[row][1], hB.y, wv.y);
                }
            }
            if (c < 7) {
                const int nb = buf ^ 1;
                #pragma unroll
                for (int i = 0; i < 4; i++)
                    *(float4*)&HwP[(nb * 64 + lb + 16 * i) * HST + lq * 4] = r4[i];
            }
            asm volatile("bar.sync %0, 64;" :: "r"(p + 1) : "memory");
        }

        // partials -> Red[p][row][b]
        #pragma unroll
        for (int row = 0; row < 12; row++) {
            float* R = Red + (size_t)(p * NROW + rbase + row) * REDS;
            R[lane]      = sum2(acc[row][0]);
            R[lane + 32] = sum2(acc[row][1]);
        }
        __syncthreads();

        // fused gate epilogue: one output per thread
        {
            float sr = 0.f, sz = 0.f, sn = 0.f;
            #pragma unroll
            for (int s = 0; s < NPAIR; s++) {
                const float* R = Red + (size_t)s * NROW * REDS;
                sr += R[(0 * 8 + ejj) * REDS + eb];
                sz += R[(1 * 8 + ejj) * REDS + eb];
                sn += R[(2 * 8 + ejj) * REDS + eb];
            }
            float r = 1.f / (1.f + expf(-(xr + sr + bhr)));
            float z = 1.f / (1.f + expf(-(xz + sz + bhz)));
            float n = tanhf(xn + r * (sn + bhn));
            float hnew = (1.f - z) * n + z * hpv;
            __stcg(&ho[(size_t)eb * H_SZ + ej], hnew);
            if (t == T_LEN - 1)
                __stcg(&hn_out[(size_t)eb * H_SZ + ej], hnew);
            hpv = hnew;
        }

        // ---- grid-wide sync ----
        __threadfence();
        __syncthreads();
        if (tid == 0) {
            asm volatile("red.release.gpu.global.add.u32 [%0], %1;"
                         :: "l"(&g_sync), "r"(1u) : "memory");
            unsigned v;
            do {
                asm volatile("ld.acquire.gpu.global.u32 %0, [%1];"
                             : "=r"(v) : "l"(&g_sync) : "memory");
            } while (v < target);
        }
        __syncthreads();
        target += NBLK;
    }
}

extern "C" void kernel_launch(void* const* d_in, const int* in_sizes, int n_in,
                              void* d_out, int out_size)
{
    const float* x    = (const float*)d_in[0];   // (T, B, I)
    const float* w_ih = (const float*)d_in[1];   // (3H, I)
    const float* w_hh = (const float*)d_in[2];   // (3H, H)
    const float* b_ih = (const float*)d_in[3];   // (3H,)
    const float* b_hh = (const float*)d_in[4];   // (3H,)
    float* out = (float*)d_out;

    // reset the grid-sync counter (graph-capturable H2D memcpy)
    static unsigned h_zero = 0;
    void* sync_addr = nullptr;
    cudaGetSymbolAddress(&sync_addr, g_sync);
    cudaMemcpyAsync(sync_addr, &h_zero, sizeof(unsigned),
                    cudaMemcpyHostToDevice, 0);

    // Phase 1: input projection GEMM
    dim3 gridA(G3H / 128, M_TOT / 128);
    gemm_xgates<<<gridA, 256>>>(x, w_ih, b_ih);

    // Phase 2: persistent recurrent scan (all 512 steps in one kernel)
    const int smem_bytes = (NROW * H_SZ + NPAIR * 2 * 64 * HST + NPAIR * NROW * REDS)
                           * (int)sizeof(float);
    cudaFuncSetAttribute(gru_persistent,
                         cudaFuncAttributeMaxDynamicSharedMemorySize, smem_bytes);
    gru_persistent<<<NBLK, 512, smem_bytes>>>(out, w_hh, b_hh);
}